// round 12
// baseline (speedup 1.0000x reference)
#include <cuda_runtime.h>
#include <cuda_fp16.h>

#define NN 50000
#define EE 800000
#define HIDD 64
#define HC 256

// ---------------- device scratch (static, no allocation) ----------------
__device__ __align__(16) __half g_xh[NN * HC];      // per-layer features fp16
__device__ __align__(16) float g_alphap[EE * 4];    // exp(alpha) in CSR order
__device__ int g_srcp[EE];                          // src per CSR position
__device__ int g_dstp[EE];                          // dst per CSR position
__device__ float g_eap[EE * 3];                     // edge_attr in CSR order
__device__ __align__(16) float g_asrc[NN * 4];
__device__ __align__(16) float g_adst[NN * 4];
__device__ __align__(16) float g_zbuf[NN * HIDD];   // inter-layer z
__device__ int g_src[EE];
__device__ int g_dst[EE];
__device__ int g_deg[NN];
__device__ int g_excl[NN];
__device__ int g_rowptr[NN + 1];
__device__ int g_wpos[NN];
__device__ int g_btot[64];
__device__ int g_boff[64];
__device__ float g_Wae[24];
__device__ int g_is32;

__device__ __forceinline__ float lrelu(float v) { return v > 0.f ? v : 0.2f * v; }

#define FMA_F32X2(d, a, b, c) \
    asm("fma.rn.f32x2 %0, %1, %2, %3;" : "=l"(d) : "l"(a), "l"(b), "l"(c))
#define PACK2(out, lo, hi) \
    asm("mov.b64 %0, {%1, %2};" : "=l"(out) : "r"(lo), "r"(hi))
#define UNPACK2(lo, hi, in) \
    asm("mov.b64 {%0, %1}, %2;" : "=r"(lo), "=r"(hi) : "l"(in))

// ---------------- detect dtype + zero degree (fused) --------------------
__global__ void k_detect_zero(const void* __restrict__ ei) {
    int i = blockIdx.x * blockDim.x + threadIdx.x;
    if (i < NN) g_deg[i] = 0;
    if (blockIdx.x == 0 && threadIdx.x == 0) g_is32 = 0;
    if (blockIdx.x == 1) {
        const long long* p = (const long long*)ei;
        long long v = p[threadIdx.x];
        if (v < 0 || v >= NN) atomicExch(&g_is32, 1);
    }
}

// ---------------- CSR build ----------------
__global__ void k_convert(const void* __restrict__ ei) {
    int e = blockIdx.x * blockDim.x + threadIdx.x;
    if (e >= EE) return;
    int s, d;
    if (g_is32) {
        const int* p = (const int*)ei;
        s = p[e];
        d = p[EE + e];
    } else {
        const long long* p = (const long long*)ei;
        s = (int)p[e];
        d = (int)p[EE + e];
    }
    s = (s < 0) ? 0 : (s >= NN ? NN - 1 : s);
    d = (d < 0) ? 0 : (d >= NN ? NN - 1 : d);
    g_src[e] = s;
    g_dst[e] = d;
    atomicAdd(&g_deg[d], 1);
}

__global__ void k_scan1() {
    __shared__ int s[1024];
    int t = threadIdx.x;
    int i = blockIdx.x * 1024 + t;
    int v = (i < NN) ? g_deg[i] : 0;
    s[t] = v;
    __syncthreads();
    for (int off = 1; off < 1024; off <<= 1) {
        int tv = (t >= off) ? s[t - off] : 0;
        __syncthreads();
        s[t] += tv;
        __syncthreads();
    }
    if (i < NN) g_excl[i] = s[t] - v;
    if (t == 1023) g_btot[blockIdx.x] = s[1023];
}

// scan2 (thread 0) + Wae fold (warp per output, 24 warps) fused
__global__ void k_scan2_wae(int nb, const float* __restrict__ att_edge,
                            const float* __restrict__ lin_edge_W) {
    int t = threadIdx.x;
    if (t == 0) {
        int run = 0;
        for (int b = 0; b < nb; b++) { g_boff[b] = run; run += g_btot[b]; }
        g_rowptr[NN] = run;
    }
    int w = t >> 5;
    int lane = t & 31;
    if (w < 24) {
        int l = w / 12;
        int r = w % 12;
        int d = r / 4;
        int h = r % 4;
        float acc = 0.f;
#pragma unroll
        for (int cc = 0; cc < 2; cc++) {
            int c = lane + 32 * cc;
            acc += att_edge[l * 256 + h * 64 + c] * lin_edge_W[l * 768 + (h * 64 + c) * 3 + d];
        }
#pragma unroll
        for (int off = 16; off > 0; off >>= 1)
            acc += __shfl_xor_sync(0xffffffffu, acc, off);
        if (lane == 0) g_Wae[l * 12 + d * 4 + h] = acc;
    }
}

__global__ void k_scan3() {
    int i = blockIdx.x * blockDim.x + threadIdx.x;
    if (i < NN) {
        int v = g_excl[i] + g_boff[i >> 10];
        g_rowptr[i] = v;
        g_wpos[i] = v;
    }
}

// scatter: place src/dst/edge_attr directly at CSR slot
__global__ void k_scatter(const float* __restrict__ ea) {
    int e = blockIdx.x * blockDim.x + threadIdx.x;
    if (e >= EE) return;
    int d = g_dst[e];
    int s = g_src[e];
    float e0 = ea[3 * e], e1 = ea[3 * e + 1], e2 = ea[3 * e + 2];
    int p = atomicAdd(&g_wpos[d], 1);
    g_srcp[p] = s;
    g_dstp[p] = d;
    g_eap[3 * p] = e0;
    g_eap[3 * p + 1] = e1;
    g_eap[3 * p + 2] = e2;
}

// ---------------- GEMM: x = z @ W^T, f32x2 k-pair split accumulators ----
__global__ void k_gemm(const float* __restrict__ hin, int layer,
                       const float* __restrict__ linW,
                       const float* __restrict__ attS,
                       const float* __restrict__ attD) {
    __shared__ float2 Wsm2[32 * 128];  // [32 k-pairs][128 cols], 32 KB
    const int half_ = blockIdx.y;
    const float* zin = (layer == 0) ? hin : g_zbuf;
    int tid = threadIdx.x;
    const float2* lw2 = reinterpret_cast<const float2*>(linW);
    for (int idx = tid; idx < 128 * 32; idx += 256) {
        int kp = idx & 31;
        int j = idx >> 5;
        Wsm2[kp * 128 + j] = lw2[(half_ * 128 + j) * 32 + kp];  // (W[2kp][j], W[2kp+1][j])
    }
    __syncthreads();
    int lane = tid & 31;
    int gw = blockIdx.x * 8 + (tid >> 5);
    int nw = gridDim.x * 8;
    for (int n4 = gw * 4; n4 < NN; n4 += nw * 4) {
        float z0[4], z1[4];
#pragma unroll
        for (int i = 0; i < 4; i++) {
            z0[i] = zin[(n4 + i) * 64 + lane];
            z1[i] = zin[(n4 + i) * 64 + 32 + lane];
        }
        unsigned long long accp[4][4];  // [node][jg], packed (even-k, odd-k)
#pragma unroll
        for (int i = 0; i < 4; i++)
#pragma unroll
            for (int j = 0; j < 4; j++) accp[i][j] = 0ull;
#pragma unroll
        for (int kp = 0; kp < 32; kp++) {
            int la = (2 * kp) & 31;
            int lb = (2 * kp + 1) & 31;
            unsigned long long zz[4];
#pragma unroll
            for (int i = 0; i < 4; i++) {
                float za = __shfl_sync(0xffffffffu, (kp < 16) ? z0[i] : z1[i], la);
                float zb = __shfl_sync(0xffffffffu, (kp < 16) ? z0[i] : z1[i], lb);
                PACK2(zz[i], __float_as_uint(za), __float_as_uint(zb));
            }
#pragma unroll
            for (int jg = 0; jg < 4; jg++) {
                unsigned long long w2 =
                    *reinterpret_cast<const unsigned long long*>(&Wsm2[kp * 128 + lane + 32 * jg]);
#pragma unroll
                for (int i = 0; i < 4; i++) FMA_F32X2(accp[i][jg], zz[i], w2, accp[i][jg]);
            }
        }
        float acc[4][4];
#pragma unroll
        for (int i = 0; i < 4; i++)
#pragma unroll
            for (int j = 0; j < 4; j++) {
                unsigned lo, hi;
                UNPACK2(lo, hi, accp[i][j]);
                acc[i][j] = __uint_as_float(lo) + __uint_as_float(hi);
            }
#pragma unroll
        for (int i = 0; i < 4; i++) {
            int n = n4 + i;
#pragma unroll
            for (int j = 0; j < 4; j++)
                g_xh[n * 256 + half_ * 128 + lane + 32 * j] = __float2half(acc[i][j]);
            float ps[2], pd[2];
#pragma unroll
            for (int hl = 0; hl < 2; hl++) {
                int h = half_ * 2 + hl;
                float s0 = attS[h * 64 + lane], s1 = attS[h * 64 + 32 + lane];
                float d0 = attD[h * 64 + lane], d1 = attD[h * 64 + 32 + lane];
                ps[hl] = acc[i][2 * hl] * s0 + acc[i][2 * hl + 1] * s1;
                pd[hl] = acc[i][2 * hl] * d0 + acc[i][2 * hl + 1] * d1;
            }
#pragma unroll
            for (int hl = 0; hl < 2; hl++) {
#pragma unroll
                for (int off = 16; off > 0; off >>= 1) {
                    ps[hl] += __shfl_xor_sync(0xffffffffu, ps[hl], off);
                    pd[hl] += __shfl_xor_sync(0xffffffffu, pd[hl], off);
                }
            }
            if (lane == 0) {
                *reinterpret_cast<float2*>(g_asrc + 4 * n + half_ * 2) = make_float2(ps[0], ps[1]);
                *reinterpret_cast<float2*>(g_adst + 4 * n + half_ * 2) = make_float2(pd[0], pd[1]);
            }
        }
    }
}

// ---------------- pass A: exp(alpha), fully coalesced CSR reads ---------
__global__ void k_passA(int l) {
    int p = blockIdx.x * blockDim.x + threadIdx.x;
    if (p >= EE) return;
    int s = g_srcp[p], d = g_dstp[p];
    float e0 = g_eap[3 * p], e1 = g_eap[3 * p + 1], e2 = g_eap[3 * p + 2];
    const float* W = g_Wae + l * 12;
    float4 as = *reinterpret_cast<const float4*>(g_asrc + 4 * s);
    float4 ad = *reinterpret_cast<const float4*>(g_adst + 4 * d);
    float4 al;
    al.x = __expf(lrelu(as.x + ad.x + e0 * W[0] + e1 * W[4] + e2 * W[8]));
    al.y = __expf(lrelu(as.y + ad.y + e0 * W[1] + e1 * W[5] + e2 * W[9]));
    al.z = __expf(lrelu(as.z + ad.z + e0 * W[2] + e1 * W[6] + e2 * W[10]));
    al.w = __expf(lrelu(as.w + ad.w + e0 * W[3] + e1 * W[7] + e2 * W[11]));
    *reinterpret_cast<float4*>(g_alphap + 4 * p) = al;
}

// ---------------- aggregation: warp per dst, single fused loop ----------
__global__ void k_agg(const float* __restrict__ bias, const float* __restrict__ gamma,
                      const float* __restrict__ beta, float* __restrict__ dout, int layer) {
    int gtid = blockIdx.x * blockDim.x + threadIdx.x;
    int n = gtid >> 5;
    if (n >= NN) return;
    int lane = gtid & 31;
    int hd = lane >> 3;
    int sub = lane & 7;
    int beg = g_rowptr[n], end = g_rowptr[n + 1];

    float a[8] = {0.f, 0.f, 0.f, 0.f, 0.f, 0.f, 0.f, 0.f};
    float dacc = 0.f;
    int p = beg;
    for (; p + 3 < end; p += 4) {
        int s0 = g_srcp[p], s1 = g_srcp[p + 1], s2 = g_srcp[p + 2], s3 = g_srcp[p + 3];
        float w0 = g_alphap[4 * p + hd];
        float w1 = g_alphap[4 * (p + 1) + hd];
        float w2 = g_alphap[4 * (p + 2) + hd];
        float w3 = g_alphap[4 * (p + 3) + hd];
        uint4 r0 = *reinterpret_cast<const uint4*>(g_xh + s0 * 256 + lane * 8);
        uint4 r1 = *reinterpret_cast<const uint4*>(g_xh + s1 * 256 + lane * 8);
        uint4 r2 = *reinterpret_cast<const uint4*>(g_xh + s2 * 256 + lane * 8);
        uint4 r3 = *reinterpret_cast<const uint4*>(g_xh + s3 * 256 + lane * 8);
        dacc += (w0 + w1) + (w2 + w3);
        const __half2* h0 = reinterpret_cast<const __half2*>(&r0);
        const __half2* h1 = reinterpret_cast<const __half2*>(&r1);
        const __half2* h2 = reinterpret_cast<const __half2*>(&r2);
        const __half2* h3 = reinterpret_cast<const __half2*>(&r3);
#pragma unroll
        for (int q = 0; q < 4; q++) {
            float2 f0 = __half22float2(h0[q]);
            float2 f1 = __half22float2(h1[q]);
            float2 f2 = __half22float2(h2[q]);
            float2 f3 = __half22float2(h3[q]);
            a[2 * q]     = fmaf(w0, f0.x, a[2 * q]);
            a[2 * q + 1] = fmaf(w0, f0.y, a[2 * q + 1]);
            a[2 * q]     = fmaf(w1, f1.x, a[2 * q]);
            a[2 * q + 1] = fmaf(w1, f1.y, a[2 * q + 1]);
            a[2 * q]     = fmaf(w2, f2.x, a[2 * q]);
            a[2 * q + 1] = fmaf(w2, f2.y, a[2 * q + 1]);
            a[2 * q]     = fmaf(w3, f3.x, a[2 * q]);
            a[2 * q + 1] = fmaf(w3, f3.y, a[2 * q + 1]);
        }
    }
    for (; p < end; ++p) {
        int s0 = g_srcp[p];
        float w0 = g_alphap[4 * p + hd];
        uint4 r0 = *reinterpret_cast<const uint4*>(g_xh + s0 * 256 + lane * 8);
        dacc += w0;
        const __half2* h0 = reinterpret_cast<const __half2*>(&r0);
#pragma unroll
        for (int q = 0; q < 4; q++) {
            float2 f0 = __half22float2(h0[q]);
            a[2 * q]     = fmaf(w0, f0.x, a[2 * q]);
            a[2 * q + 1] = fmaf(w0, f0.y, a[2 * q + 1]);
        }
    }
    float invd = 1.f / (dacc + 1e-16f);
#pragma unroll
    for (int q = 0; q < 8; q++) {
        a[q] *= invd;
        a[q] += __shfl_xor_sync(0xffffffffu, a[q], 8);
        a[q] += __shfl_xor_sync(0xffffffffu, a[q], 16);
    }
    float s1 = 0.f, s2 = 0.f;
#pragma unroll
    for (int i = 0; i < 8; i++) {
        a[i] = a[i] * 0.25f + bias[sub * 8 + i];
        s1 += a[i];
        s2 += a[i] * a[i];
    }
#pragma unroll
    for (int off = 1; off <= 4; off <<= 1) {
        s1 += __shfl_xor_sync(0xffffffffu, s1, off);
        s2 += __shfl_xor_sync(0xffffffffu, s2, off);
    }
    float mu = s1 * (1.f / 64.f);
    float var = s2 * (1.f / 64.f) - mu * mu;
    float rstd = rsqrtf(var + 1e-5f);
    float* zout = (layer == 1) ? dout : g_zbuf;
    if (lane < 8) {
        float res[8];
#pragma unroll
        for (int i = 0; i < 8; i++) {
            int c = sub * 8 + i;
            float ln = (a[i] - mu) * rstd * gamma[c] + beta[c];
            res[i] = ln / (1.f + __expf(-ln));
        }
        float4* op = reinterpret_cast<float4*>(zout + n * 64 + sub * 8);
        op[0] = make_float4(res[0], res[1], res[2], res[3]);
        op[1] = make_float4(res[4], res[5], res[6], res[7]);
    }
}

// ---------------- launch ----------------
extern "C" void kernel_launch(void* const* d_in, const int* in_sizes, int n_in,
                              void* d_out, int out_size) {
    const float* h = (const float*)d_in[1];
    const void* ei = d_in[2];
    const float* ea = (const float*)d_in[3];
    const float* linW = (const float*)d_in[4];
    const float* linEW = (const float*)d_in[5];
    const float* attS = (const float*)d_in[6];
    const float* attD = (const float*)d_in[7];
    const float* attE = (const float*)d_in[8];
    const float* bias = (const float*)d_in[9];
    const float* gamma = (const float*)d_in[10];
    const float* beta = (const float*)d_in[11];
    float* dout = (float*)d_out;

    k_detect_zero<<<(NN + 255) / 256, 256>>>(ei);
    k_convert<<<(EE + 255) / 256, 256>>>(ei);
    k_scan1<<<(NN + 1023) / 1024, 1024>>>();
    k_scan2_wae<<<1, 768>>>((NN + 1023) / 1024, attE, linEW);
    k_scan3<<<(NN + 255) / 256, 256>>>();
    k_scatter<<<(EE + 255) / 256, 256>>>(ea);

    for (int l = 0; l < 2; l++) {
        k_gemm<<<dim3(296, 2), 256>>>(h, l, linW + l * 256 * 64, attS + l * 256, attD + l * 256);
        k_passA<<<(EE + 255) / 256, 256>>>(l);
        k_agg<<<(NN * 32 + 255) / 256, 256>>>(bias + l * 64, gamma + l * 64, beta + l * 64, dout, l);
    }
}

// round 14
// speedup vs baseline: 1.0006x; 1.0006x over previous
#include <cuda_runtime.h>
#include <cuda_fp16.h>

#define NN 50000
#define EE 800000
#define HIDD 64
#define HC 256

// ---------------- device scratch (static, no allocation) ----------------
__device__ __align__(16) __half g_xh[NN * HC];      // per-layer features fp16
__device__ int g_srcp[EE];                          // src per CSR position
__device__ __align__(16) float g_aeh[EE * 8];       // a_e per CSR pos [p][l][h]
__device__ __align__(16) float g_asrc[NN * 4];
__device__ __align__(16) float g_adst[NN * 4];
__device__ __align__(16) float g_zbuf[NN * HIDD];   // inter-layer z
__device__ int g_src[EE];
__device__ int g_dst[EE];
__device__ int g_deg[NN];
__device__ int g_excl[NN];
__device__ int g_rowptr[NN + 1];
__device__ int g_wpos[NN];
__device__ int g_btot[64];
__device__ int g_boff[64];
__device__ float g_Wae[24];
__device__ int g_is32;

__device__ __forceinline__ float lrelu(float v) { return v > 0.f ? v : 0.2f * v; }

#define FMA_F32X2(d, a, b, c) \
    asm("fma.rn.f32x2 %0, %1, %2, %3;" : "=l"(d) : "l"(a), "l"(b), "l"(c))
#define PACK2(out, lo, hi) \
    asm("mov.b64 %0, {%1, %2};" : "=l"(out) : "r"(lo), "r"(hi))
#define UNPACK2(lo, hi, in) \
    asm("mov.b64 {%0, %1}, %2;" : "=r"(lo), "=r"(hi) : "l"(in))

// ---------------- detect dtype + zero degree (fused) --------------------
__global__ void k_detect_zero(const void* __restrict__ ei) {
    int i = blockIdx.x * blockDim.x + threadIdx.x;
    if (i < NN) g_deg[i] = 0;
    if (blockIdx.x == 0 && threadIdx.x == 0) g_is32 = 0;
    if (blockIdx.x == 1) {
        const long long* p = (const long long*)ei;
        long long v = p[threadIdx.x];
        if (v < 0 || v >= NN) atomicExch(&g_is32, 1);
    }
}

// ---------------- CSR build ----------------
__global__ void k_convert(const void* __restrict__ ei) {
    int e = blockIdx.x * blockDim.x + threadIdx.x;
    if (e >= EE) return;
    int s, d;
    if (g_is32) {
        const int* p = (const int*)ei;
        s = p[e];
        d = p[EE + e];
    } else {
        const long long* p = (const long long*)ei;
        s = (int)p[e];
        d = (int)p[EE + e];
    }
    s = (s < 0) ? 0 : (s >= NN ? NN - 1 : s);
    d = (d < 0) ? 0 : (d >= NN ? NN - 1 : d);
    g_src[e] = s;
    g_dst[e] = d;
    atomicAdd(&g_deg[d], 1);
}

__global__ void k_scan1() {
    __shared__ int s[1024];
    int t = threadIdx.x;
    int i = blockIdx.x * 1024 + t;
    int v = (i < NN) ? g_deg[i] : 0;
    s[t] = v;
    __syncthreads();
    for (int off = 1; off < 1024; off <<= 1) {
        int tv = (t >= off) ? s[t - off] : 0;
        __syncthreads();
        s[t] += tv;
        __syncthreads();
    }
    if (i < NN) g_excl[i] = s[t] - v;
    if (t == 1023) g_btot[blockIdx.x] = s[1023];
}

// scan2 (thread 0) + Wae fold (warp per output, 24 warps) fused
__global__ void k_scan2_wae(int nb, const float* __restrict__ att_edge,
                            const float* __restrict__ lin_edge_W) {
    int t = threadIdx.x;
    if (t == 0) {
        int run = 0;
        for (int b = 0; b < nb; b++) { g_boff[b] = run; run += g_btot[b]; }
        g_rowptr[NN] = run;
    }
    int w = t >> 5;
    int lane = t & 31;
    if (w < 24) {
        int l = w / 12;
        int r = w % 12;
        int d = r / 4;
        int h = r % 4;
        float acc = 0.f;
#pragma unroll
        for (int cc = 0; cc < 2; cc++) {
            int c = lane + 32 * cc;
            acc += att_edge[l * 256 + h * 64 + c] * lin_edge_W[l * 768 + (h * 64 + c) * 3 + d];
        }
#pragma unroll
        for (int off = 16; off > 0; off >>= 1)
            acc += __shfl_xor_sync(0xffffffffu, acc, off);
        if (lane == 0) g_Wae[l * 12 + d * 4 + h] = acc;
    }
}

__global__ void k_scan3() {
    int i = blockIdx.x * blockDim.x + threadIdx.x;
    if (i < NN) {
        int v = g_excl[i] + g_boff[i >> 10];
        g_rowptr[i] = v;
        g_wpos[i] = v;
    }
}

// scatter: place src + per-layer per-head edge logits at CSR slot
__global__ void k_scatter(const float* __restrict__ ea) {
    int e = blockIdx.x * blockDim.x + threadIdx.x;
    if (e >= EE) return;
    int d = g_dst[e];
    int s = g_src[e];
    float e0 = ea[3 * e], e1 = ea[3 * e + 1], e2 = ea[3 * e + 2];
    int p = atomicAdd(&g_wpos[d], 1);
    g_srcp[p] = s;
#pragma unroll
    for (int l = 0; l < 2; l++) {
        const float* W = g_Wae + l * 12;
        float4 v;
        v.x = e0 * W[0] + e1 * W[4] + e2 * W[8];
        v.y = e0 * W[1] + e1 * W[5] + e2 * W[9];
        v.z = e0 * W[2] + e1 * W[6] + e2 * W[10];
        v.w = e0 * W[3] + e1 * W[7] + e2 * W[11];
        *reinterpret_cast<float4*>(g_aeh + (p * 2 + l) * 4) = v;
    }
}

// ---------------- GEMM: x = z @ W^T, f32x2 k-pair split accumulators ----
__global__ void k_gemm(const float* __restrict__ hin, int layer,
                       const float* __restrict__ linW,
                       const float* __restrict__ attS,
                       const float* __restrict__ attD) {
    __shared__ float2 Wsm2[32 * 128];  // [32 k-pairs][128 cols], 32 KB
    const int half_ = blockIdx.y;
    const float* zin = (layer == 0) ? hin : g_zbuf;
    int tid = threadIdx.x;
    const float2* lw2 = reinterpret_cast<const float2*>(linW);
    for (int idx = tid; idx < 128 * 32; idx += 256) {
        int kp = idx & 31;
        int j = idx >> 5;
        Wsm2[kp * 128 + j] = lw2[(half_ * 128 + j) * 32 + kp];
    }
    __syncthreads();
    int lane = tid & 31;
    int gw = blockIdx.x * 8 + (tid >> 5);
    int nw = gridDim.x * 8;
    for (int n4 = gw * 4; n4 < NN; n4 += nw * 4) {
        float z0[4], z1[4];
#pragma unroll
        for (int i = 0; i < 4; i++) {
            z0[i] = zin[(n4 + i) * 64 + lane];
            z1[i] = zin[(n4 + i) * 64 + 32 + lane];
        }
        unsigned long long accp[4][4];
#pragma unroll
        for (int i = 0; i < 4; i++)
#pragma unroll
            for (int j = 0; j < 4; j++) accp[i][j] = 0ull;
#pragma unroll
        for (int kp = 0; kp < 32; kp++) {
            int la = (2 * kp) & 31;
            int lb = (2 * kp + 1) & 31;
            unsigned long long zz[4];
#pragma unroll
            for (int i = 0; i < 4; i++) {
                float za = __shfl_sync(0xffffffffu, (kp < 16) ? z0[i] : z1[i], la);
                float zb = __shfl_sync(0xffffffffu, (kp < 16) ? z0[i] : z1[i], lb);
                PACK2(zz[i], __float_as_uint(za), __float_as_uint(zb));
            }
#pragma unroll
            for (int jg = 0; jg < 4; jg++) {
                unsigned long long w2 =
                    *reinterpret_cast<const unsigned long long*>(&Wsm2[kp * 128 + lane + 32 * jg]);
#pragma unroll
                for (int i = 0; i < 4; i++) FMA_F32X2(accp[i][jg], zz[i], w2, accp[i][jg]);
            }
        }
        float acc[4][4];
#pragma unroll
        for (int i = 0; i < 4; i++)
#pragma unroll
            for (int j = 0; j < 4; j++) {
                unsigned lo, hi;
                UNPACK2(lo, hi, accp[i][j]);
                acc[i][j] = __uint_as_float(lo) + __uint_as_float(hi);
            }
#pragma unroll
        for (int i = 0; i < 4; i++) {
            int n = n4 + i;
#pragma unroll
            for (int j = 0; j < 4; j++)
                g_xh[n * 256 + half_ * 128 + lane + 32 * j] = __float2half(acc[i][j]);
            float ps[2], pd[2];
#pragma unroll
            for (int hl = 0; hl < 2; hl++) {
                int h = half_ * 2 + hl;
                float s0 = attS[h * 64 + lane], s1 = attS[h * 64 + 32 + lane];
                float d0 = attD[h * 64 + lane], d1 = attD[h * 64 + 32 + lane];
                ps[hl] = acc[i][2 * hl] * s0 + acc[i][2 * hl + 1] * s1;
                pd[hl] = acc[i][2 * hl] * d0 + acc[i][2 * hl + 1] * d1;
            }
#pragma unroll
            for (int hl = 0; hl < 2; hl++) {
#pragma unroll
                for (int off = 16; off > 0; off >>= 1) {
                    ps[hl] += __shfl_xor_sync(0xffffffffu, ps[hl], off);
                    pd[hl] += __shfl_xor_sync(0xffffffffu, pd[hl], off);
                }
            }
            if (lane == 0) {
                *reinterpret_cast<float2*>(g_asrc + 4 * n + half_ * 2) = make_float2(ps[0], ps[1]);
                *reinterpret_cast<float2*>(g_adst + 4 * n + half_ * 2) = make_float2(pd[0], pd[1]);
            }
        }
    }
}

// ---------------- aggregation: warp per dst, inline attention -----------
__global__ void k_agg(const float* __restrict__ bias, const float* __restrict__ gamma,
                      const float* __restrict__ beta, float* __restrict__ dout, int layer) {
    int gtid = blockIdx.x * blockDim.x + threadIdx.x;
    int n = gtid >> 5;
    if (n >= NN) return;
    int lane = gtid & 31;
    int hd = lane >> 3;
    int sub = lane & 7;
    int beg = g_rowptr[n], end = g_rowptr[n + 1];
    float adsth = g_adst[4 * n + hd];  // warp-group constant

    float a[8] = {0.f, 0.f, 0.f, 0.f, 0.f, 0.f, 0.f, 0.f};
    float dacc = 0.f;
    int p = beg;
    for (; p + 3 < end; p += 4) {
        int s0 = g_srcp[p], s1 = g_srcp[p + 1], s2 = g_srcp[p + 2], s3 = g_srcp[p + 3];
        float ae0 = g_aeh[(p * 2 + layer) * 4 + hd];
        float ae1 = g_aeh[((p + 1) * 2 + layer) * 4 + hd];
        float ae2 = g_aeh[((p + 2) * 2 + layer) * 4 + hd];
        float ae3 = g_aeh[((p + 3) * 2 + layer) * 4 + hd];
        float as0 = g_asrc[4 * s0 + hd];
        float as1 = g_asrc[4 * s1 + hd];
        float as2 = g_asrc[4 * s2 + hd];
        float as3 = g_asrc[4 * s3 + hd];
        uint4 r0 = *reinterpret_cast<const uint4*>(g_xh + s0 * 256 + lane * 8);
        uint4 r1 = *reinterpret_cast<const uint4*>(g_xh + s1 * 256 + lane * 8);
        uint4 r2 = *reinterpret_cast<const uint4*>(g_xh + s2 * 256 + lane * 8);
        uint4 r3 = *reinterpret_cast<const uint4*>(g_xh + s3 * 256 + lane * 8);
        float w0 = __expf(lrelu(as0 + adsth + ae0));
        float w1 = __expf(lrelu(as1 + adsth + ae1));
        float w2 = __expf(lrelu(as2 + adsth + ae2));
        float w3 = __expf(lrelu(as3 + adsth + ae3));
        dacc += (w0 + w1) + (w2 + w3);
        const __half2* h0 = reinterpret_cast<const __half2*>(&r0);
        const __half2* h1 = reinterpret_cast<const __half2*>(&r1);
        const __half2* h2 = reinterpret_cast<const __half2*>(&r2);
        const __half2* h3 = reinterpret_cast<const __half2*>(&r3);
#pragma unroll
        for (int q = 0; q < 4; q++) {
            float2 f0 = __half22float2(h0[q]);
            float2 f1 = __half22float2(h1[q]);
            float2 f2 = __half22float2(h2[q]);
            float2 f3 = __half22float2(h3[q]);
            a[2 * q]     = fmaf(w0, f0.x, a[2 * q]);
            a[2 * q + 1] = fmaf(w0, f0.y, a[2 * q + 1]);
            a[2 * q]     = fmaf(w1, f1.x, a[2 * q]);
            a[2 * q + 1] = fmaf(w1, f1.y, a[2 * q + 1]);
            a[2 * q]     = fmaf(w2, f2.x, a[2 * q]);
            a[2 * q + 1] = fmaf(w2, f2.y, a[2 * q + 1]);
            a[2 * q]     = fmaf(w3, f3.x, a[2 * q]);
            a[2 * q + 1] = fmaf(w3, f3.y, a[2 * q + 1]);
        }
    }
    for (; p < end; ++p) {
        int s0 = g_srcp[p];
        float ae0 = g_aeh[(p * 2 + layer) * 4 + hd];
        float as0 = g_asrc[4 * s0 + hd];
        uint4 r0 = *reinterpret_cast<const uint4*>(g_xh + s0 * 256 + lane * 8);
        float w0 = __expf(lrelu(as0 + adsth + ae0));
        dacc += w0;
        const __half2* h0 = reinterpret_cast<const __half2*>(&r0);
#pragma unroll
        for (int q = 0; q < 4; q++) {
            float2 f0 = __half22float2(h0[q]);
            a[2 * q]     = fmaf(w0, f0.x, a[2 * q]);
            a[2 * q + 1] = fmaf(w0, f0.y, a[2 * q + 1]);
        }
    }
    float invd = 1.f / (dacc + 1e-16f);
#pragma unroll
    for (int q = 0; q < 8; q++) {
        a[q] *= invd;
        a[q] += __shfl_xor_sync(0xffffffffu, a[q], 8);
        a[q] += __shfl_xor_sync(0xffffffffu, a[q], 16);
    }
    float s1 = 0.f, s2 = 0.f;
#pragma unroll
    for (int i = 0; i < 8; i++) {
        a[i] = a[i] * 0.25f + bias[sub * 8 + i];
        s1 += a[i];
        s2 += a[i] * a[i];
    }
#pragma unroll
    for (int off = 1; off <= 4; off <<= 1) {
        s1 += __shfl_xor_sync(0xffffffffu, s1, off);
        s2 += __shfl_xor_sync(0xffffffffu, s2, off);
    }
    float mu = s1 * (1.f / 64.f);
    float var = s2 * (1.f / 64.f) - mu * mu;
    float rstd = rsqrtf(var + 1e-5f);
    float* zout = (layer == 1) ? dout : g_zbuf;
    if (lane < 8) {
        float res[8];
#pragma unroll
        for (int i = 0; i < 8; i++) {
            int c = sub * 8 + i;
            float ln = (a[i] - mu) * rstd * gamma[c] + beta[c];
            res[i] = ln / (1.f + __expf(-ln));
        }
        float4* op = reinterpret_cast<float4*>(zout + n * 64 + sub * 8);
        op[0] = make_float4(res[0], res[1], res[2], res[3]);
        op[1] = make_float4(res[4], res[5], res[6], res[7]);
    }
}

// ---------------- launch ----------------
extern "C" void kernel_launch(void* const* d_in, const int* in_sizes, int n_in,
                              void* d_out, int out_size) {
    const float* h = (const float*)d_in[1];
    const void* ei = d_in[2];
    const float* ea = (const float*)d_in[3];
    const float* linW = (const float*)d_in[4];
    const float* linEW = (const float*)d_in[5];
    const float* attS = (const float*)d_in[6];
    const float* attD = (const float*)d_in[7];
    const float* attE = (const float*)d_in[8];
    const float* bias = (const float*)d_in[9];
    const float* gamma = (const float*)d_in[10];
    const float* beta = (const float*)d_in[11];
    float* dout = (float*)d_out;

    k_detect_zero<<<(NN + 255) / 256, 256>>>(ei);
    k_convert<<<(EE + 255) / 256, 256>>>(ei);
    k_scan1<<<(NN + 1023) / 1024, 1024>>>();
    k_scan2_wae<<<1, 768>>>((NN + 1023) / 1024, attE, linEW);
    k_scan3<<<(NN + 255) / 256, 256>>>();
    k_scatter<<<(EE + 255) / 256, 256>>>(ea);

    for (int l = 0; l < 2; l++) {
        k_gemm<<<dim3(296, 2), 256>>>(h, l, linW + l * 256 * 64, attS + l * 256, attD + l * 256);
        k_agg<<<(NN * 32 + 255) / 256, 256>>>(bias + l * 64, gamma + l * 64, beta + l * 64, dout, l);
    }
}

// round 15
// speedup vs baseline: 1.0330x; 1.0324x over previous
#include <cuda_runtime.h>
#include <cuda_fp16.h>

#define NN 50000
#define EE 800000
#define HIDD 64
#define HC 256

// ---------------- device scratch (static, no allocation) ----------------
__device__ __align__(16) __half g_xh[NN * HC];      // per-layer features fp16
__device__ int g_srcp[EE];                          // src per CSR position
__device__ __align__(16) float g_aeh[EE * 8];       // a_e per CSR pos [p][l][h]
__device__ __align__(16) float g_asrc[NN * 4];
__device__ __align__(16) float g_adst[NN * 4];
__device__ __align__(16) float g_zbuf[NN * HIDD];   // inter-layer z
__device__ int g_src[EE];
__device__ int g_dst[EE];
__device__ int g_deg[NN];
__device__ int g_excl[NN];
__device__ int g_rowptr[NN + 1];
__device__ int g_wpos[NN];
__device__ int g_btot[64];
__device__ int g_boff[64];
__device__ float g_Wae[24];
__device__ int g_is32;

__device__ __forceinline__ float lrelu(float v) { return v > 0.f ? v : 0.2f * v; }

#define FMA_F32X2(d, a, b, c) \
    asm("fma.rn.f32x2 %0, %1, %2, %3;" : "=l"(d) : "l"(a), "l"(b), "l"(c))
#define UNPACK2(lo, hi, in) \
    asm("mov.b64 {%0, %1}, %2;" : "=r"(lo), "=r"(hi) : "l"(in))

// ---------------- detect dtype + zero degree (fused) --------------------
__global__ void k_detect_zero(const void* __restrict__ ei) {
    int i = blockIdx.x * blockDim.x + threadIdx.x;
    if (i < NN) g_deg[i] = 0;
    if (blockIdx.x == 0 && threadIdx.x == 0) g_is32 = 0;
    if (blockIdx.x == 1) {
        const long long* p = (const long long*)ei;
        long long v = p[threadIdx.x];
        if (v < 0 || v >= NN) atomicExch(&g_is32, 1);
    }
}

// ---------------- CSR build ----------------
__global__ void k_convert(const void* __restrict__ ei) {
    int e = blockIdx.x * blockDim.x + threadIdx.x;
    if (e >= EE) return;
    int s, d;
    if (g_is32) {
        const int* p = (const int*)ei;
        s = p[e];
        d = p[EE + e];
    } else {
        const long long* p = (const long long*)ei;
        s = (int)p[e];
        d = (int)p[EE + e];
    }
    s = (s < 0) ? 0 : (s >= NN ? NN - 1 : s);
    d = (d < 0) ? 0 : (d >= NN ? NN - 1 : d);
    g_src[e] = s;
    g_dst[e] = d;
    atomicAdd(&g_deg[d], 1);
}

__global__ void k_scan1() {
    __shared__ int s[1024];
    int t = threadIdx.x;
    int i = blockIdx.x * 1024 + t;
    int v = (i < NN) ? g_deg[i] : 0;
    s[t] = v;
    __syncthreads();
    for (int off = 1; off < 1024; off <<= 1) {
        int tv = (t >= off) ? s[t - off] : 0;
        __syncthreads();
        s[t] += tv;
        __syncthreads();
    }
    if (i < NN) g_excl[i] = s[t] - v;
    if (t == 1023) g_btot[blockIdx.x] = s[1023];
}

// scan2 (thread 0) + Wae fold (warp per output) fused
__global__ void k_scan2_wae(int nb, const float* __restrict__ att_edge,
                            const float* __restrict__ lin_edge_W) {
    int t = threadIdx.x;
    if (t == 0) {
        int run = 0;
        for (int b = 0; b < nb; b++) { g_boff[b] = run; run += g_btot[b]; }
        g_rowptr[NN] = run;
    }
    int w = t >> 5;
    int lane = t & 31;
    if (w < 24) {
        int l = w / 12;
        int r = w % 12;
        int d = r / 4;
        int h = r % 4;
        float acc = 0.f;
#pragma unroll
        for (int cc = 0; cc < 2; cc++) {
            int c = lane + 32 * cc;
            acc += att_edge[l * 256 + h * 64 + c] * lin_edge_W[l * 768 + (h * 64 + c) * 3 + d];
        }
#pragma unroll
        for (int off = 16; off > 0; off >>= 1)
            acc += __shfl_xor_sync(0xffffffffu, acc, off);
        if (lane == 0) g_Wae[l * 12 + d * 4 + h] = acc;
    }
}

__global__ void k_scan3() {
    int i = blockIdx.x * blockDim.x + threadIdx.x;
    if (i < NN) {
        int v = g_excl[i] + g_boff[i >> 10];
        g_rowptr[i] = v;
        g_wpos[i] = v;
    }
}

// scatter: place src + per-layer per-head edge logits at CSR slot
__global__ void k_scatter(const float* __restrict__ ea) {
    int e = blockIdx.x * blockDim.x + threadIdx.x;
    if (e >= EE) return;
    int d = g_dst[e];
    int s = g_src[e];
    float e0 = ea[3 * e], e1 = ea[3 * e + 1], e2 = ea[3 * e + 2];
    int p = atomicAdd(&g_wpos[d], 1);
    g_srcp[p] = s;
#pragma unroll
    for (int l = 0; l < 2; l++) {
        const float* W = g_Wae + l * 12;
        float4 v;
        v.x = e0 * W[0] + e1 * W[4] + e2 * W[8];
        v.y = e0 * W[1] + e1 * W[5] + e2 * W[9];
        v.z = e0 * W[2] + e1 * W[6] + e2 * W[10];
        v.w = e0 * W[3] + e1 * W[7] + e2 * W[11];
        *reinterpret_cast<float4*>(g_aeh + (p * 2 + l) * 4) = v;
    }
}

// ---------------- GEMM: x = z @ W^T, z broadcast via smem (no shuffles) -
// Block: 256 thr = 8 warps, handles 32-node tiles. smem: W 32 KB + z 8 KB.
__global__ void k_gemm(const float* __restrict__ hin, int layer,
                       const float* __restrict__ linW,
                       const float* __restrict__ attS,
                       const float* __restrict__ attD) {
    __shared__ float2 Wsm2[32 * 128];   // [kp][col]
    __shared__ float2 Zsm[32 * 32];     // [node-in-tile][kp]
    const int half_ = blockIdx.y;
    const float* zin = (layer == 0) ? hin : g_zbuf;
    int tid = threadIdx.x;
    int lane = tid & 31;
    int wid = tid >> 5;
    const float2* lw2 = reinterpret_cast<const float2*>(linW);
    for (int idx = tid; idx < 128 * 32; idx += 256) {
        int kp = idx & 31;
        int j = idx >> 5;
        Wsm2[kp * 128 + j] = lw2[(half_ * 128 + j) * 32 + kp];
    }
    // hoist attention vectors (per lane, this half's 2 heads)
    float sa[2][2], da[2][2];
#pragma unroll
    for (int hl = 0; hl < 2; hl++) {
        int hh = half_ * 2 + hl;
        sa[hl][0] = attS[hh * 64 + lane];
        sa[hl][1] = attS[hh * 64 + 32 + lane];
        da[hl][0] = attD[hh * 64 + lane];
        da[hl][1] = attD[hh * 64 + 32 + lane];
    }
    const float4* zin4 = reinterpret_cast<const float4*>(zin);
    const int ntiles = (NN + 31) / 32;
    for (int t = blockIdx.x; t < ntiles; t += gridDim.x) {
        int n0 = t * 32;
        __syncthreads();  // previous iteration's readers done (also covers W on iter 0)
        for (int idx = tid; idx < 32 * 16; idx += 256) {
            int i = idx >> 4;
            int c4 = idx & 15;
            float4 v = (n0 + i < NN) ? zin4[(size_t)(n0 + i) * 16 + c4]
                                     : make_float4(0.f, 0.f, 0.f, 0.f);
            reinterpret_cast<float4*>(Zsm)[i * 16 + c4] = v;
        }
        __syncthreads();
        int nb = wid * 4;  // this warp's 4 nodes within the tile
        unsigned long long accp[4][4];
#pragma unroll
        for (int i = 0; i < 4; i++)
#pragma unroll
            for (int j = 0; j < 4; j++) accp[i][j] = 0ull;
#pragma unroll
        for (int kp = 0; kp < 32; kp++) {
            unsigned long long zz[4];
#pragma unroll
            for (int i = 0; i < 4; i++)
                zz[i] = *reinterpret_cast<const unsigned long long*>(&Zsm[(nb + i) * 32 + kp]);
#pragma unroll
            for (int jg = 0; jg < 4; jg++) {
                unsigned long long w2 =
                    *reinterpret_cast<const unsigned long long*>(&Wsm2[kp * 128 + lane + 32 * jg]);
#pragma unroll
                for (int i = 0; i < 4; i++) FMA_F32X2(accp[i][jg], zz[i], w2, accp[i][jg]);
            }
        }
#pragma unroll
        for (int i = 0; i < 4; i++) {
            int n = n0 + nb + i;
            if (n >= NN) break;  // warp-uniform
            float acc[4];
#pragma unroll
            for (int j = 0; j < 4; j++) {
                unsigned lo, hi;
                UNPACK2(lo, hi, accp[i][j]);
                acc[j] = __uint_as_float(lo) + __uint_as_float(hi);
            }
#pragma unroll
            for (int j = 0; j < 4; j++)
                g_xh[(size_t)n * 256 + half_ * 128 + lane + 32 * j] = __float2half(acc[j]);
            float ps[2], pd[2];
#pragma unroll
            for (int hl = 0; hl < 2; hl++) {
                ps[hl] = acc[2 * hl] * sa[hl][0] + acc[2 * hl + 1] * sa[hl][1];
                pd[hl] = acc[2 * hl] * da[hl][0] + acc[2 * hl + 1] * da[hl][1];
            }
#pragma unroll
            for (int hl = 0; hl < 2; hl++) {
#pragma unroll
                for (int off = 16; off > 0; off >>= 1) {
                    ps[hl] += __shfl_xor_sync(0xffffffffu, ps[hl], off);
                    pd[hl] += __shfl_xor_sync(0xffffffffu, pd[hl], off);
                }
            }
            if (lane == 0) {
                *reinterpret_cast<float2*>(g_asrc + 4 * n + half_ * 2) = make_float2(ps[0], ps[1]);
                *reinterpret_cast<float2*>(g_adst + 4 * n + half_ * 2) = make_float2(pd[0], pd[1]);
            }
        }
    }
}

// ---------------- aggregation: warp per dst, inline attention -----------
__global__ void k_agg(const float* __restrict__ bias, const float* __restrict__ gamma,
                      const float* __restrict__ beta, float* __restrict__ dout, int layer) {
    int gtid = blockIdx.x * blockDim.x + threadIdx.x;
    int n = gtid >> 5;
    if (n >= NN) return;
    int lane = gtid & 31;
    int hd = lane >> 3;
    int sub = lane & 7;
    int beg = g_rowptr[n], end = g_rowptr[n + 1];
    float adsth = g_adst[4 * n + hd];

    float a[8] = {0.f, 0.f, 0.f, 0.f, 0.f, 0.f, 0.f, 0.f};
    float dacc = 0.f;
    int p = beg;
    for (; p + 3 < end; p += 4) {
        int s0 = g_srcp[p], s1 = g_srcp[p + 1], s2 = g_srcp[p + 2], s3 = g_srcp[p + 3];
        float ae0 = g_aeh[(p * 2 + layer) * 4 + hd];
        float ae1 = g_aeh[((p + 1) * 2 + layer) * 4 + hd];
        float ae2 = g_aeh[((p + 2) * 2 + layer) * 4 + hd];
        float ae3 = g_aeh[((p + 3) * 2 + layer) * 4 + hd];
        float as0 = g_asrc[4 * s0 + hd];
        float as1 = g_asrc[4 * s1 + hd];
        float as2 = g_asrc[4 * s2 + hd];
        float as3 = g_asrc[4 * s3 + hd];
        uint4 r0 = *reinterpret_cast<const uint4*>(g_xh + s0 * 256 + lane * 8);
        uint4 r1 = *reinterpret_cast<const uint4*>(g_xh + s1 * 256 + lane * 8);
        uint4 r2 = *reinterpret_cast<const uint4*>(g_xh + s2 * 256 + lane * 8);
        uint4 r3 = *reinterpret_cast<const uint4*>(g_xh + s3 * 256 + lane * 8);
        float w0 = __expf(lrelu(as0 + adsth + ae0));
        float w1 = __expf(lrelu(as1 + adsth + ae1));
        float w2 = __expf(lrelu(as2 + adsth + ae2));
        float w3 = __expf(lrelu(as3 + adsth + ae3));
        dacc += (w0 + w1) + (w2 + w3);
        const __half2* h0 = reinterpret_cast<const __half2*>(&r0);
        const __half2* h1 = reinterpret_cast<const __half2*>(&r1);
        const __half2* h2 = reinterpret_cast<const __half2*>(&r2);
        const __half2* h3 = reinterpret_cast<const __half2*>(&r3);
#pragma unroll
        for (int q = 0; q < 4; q++) {
            float2 f0 = __half22float2(h0[q]);
            float2 f1 = __half22float2(h1[q]);
            float2 f2 = __half22float2(h2[q]);
            float2 f3 = __half22float2(h3[q]);
            a[2 * q]     = fmaf(w0, f0.x, a[2 * q]);
            a[2 * q + 1] = fmaf(w0, f0.y, a[2 * q + 1]);
            a[2 * q]     = fmaf(w1, f1.x, a[2 * q]);
            a[2 * q + 1] = fmaf(w1, f1.y, a[2 * q + 1]);
            a[2 * q]     = fmaf(w2, f2.x, a[2 * q]);
            a[2 * q + 1] = fmaf(w2, f2.y, a[2 * q + 1]);
            a[2 * q]     = fmaf(w3, f3.x, a[2 * q]);
            a[2 * q + 1] = fmaf(w3, f3.y, a[2 * q + 1]);
        }
    }
    for (; p < end; ++p) {
        int s0 = g_srcp[p];
        float ae0 = g_aeh[(p * 2 + layer) * 4 + hd];
        float as0 = g_asrc[4 * s0 + hd];
        uint4 r0 = *reinterpret_cast<const uint4*>(g_xh + s0 * 256 + lane * 8);
        float w0 = __expf(lrelu(as0 + adsth + ae0));
        dacc += w0;
        const __half2* h0 = reinterpret_cast<const __half2*>(&r0);
#pragma unroll
        for (int q = 0; q < 4; q++) {
            float2 f0 = __half22float2(h0[q]);
            a[2 * q]     = fmaf(w0, f0.x, a[2 * q]);
            a[2 * q + 1] = fmaf(w0, f0.y, a[2 * q + 1]);
        }
    }
    float invd = 1.f / (dacc + 1e-16f);
#pragma unroll
    for (int q = 0; q < 8; q++) {
        a[q] *= invd;
        a[q] += __shfl_xor_sync(0xffffffffu, a[q], 8);
        a[q] += __shfl_xor_sync(0xffffffffu, a[q], 16);
    }
    float s1 = 0.f, s2 = 0.f;
#pragma unroll
    for (int i = 0; i < 8; i++) {
        a[i] = a[i] * 0.25f + bias[sub * 8 + i];
        s1 += a[i];
        s2 += a[i] * a[i];
    }
#pragma unroll
    for (int off = 1; off <= 4; off <<= 1) {
        s1 += __shfl_xor_sync(0xffffffffu, s1, off);
        s2 += __shfl_xor_sync(0xffffffffu, s2, off);
    }
    float mu = s1 * (1.f / 64.f);
    float var = s2 * (1.f / 64.f) - mu * mu;
    float rstd = rsqrtf(var + 1e-5f);
    float* zout = (layer == 1) ? dout : g_zbuf;
    if (lane < 8) {
        float res[8];
#pragma unroll
        for (int i = 0; i < 8; i++) {
            int c = sub * 8 + i;
            float ln = (a[i] - mu) * rstd * gamma[c] + beta[c];
            res[i] = ln / (1.f + __expf(-ln));
        }
        float4* op = reinterpret_cast<float4*>(zout + n * 64 + sub * 8);
        op[0] = make_float4(res[0], res[1], res[2], res[3]);
        op[1] = make_float4(res[4], res[5], res[6], res[7]);
    }
}

// ---------------- launch ----------------
extern "C" void kernel_launch(void* const* d_in, const int* in_sizes, int n_in,
                              void* d_out, int out_size) {
    const float* h = (const float*)d_in[1];
    const void* ei = d_in[2];
    const float* ea = (const float*)d_in[3];
    const float* linW = (const float*)d_in[4];
    const float* linEW = (const float*)d_in[5];
    const float* attS = (const float*)d_in[6];
    const float* attD = (const float*)d_in[7];
    const float* attE = (const float*)d_in[8];
    const float* bias = (const float*)d_in[9];
    const float* gamma = (const float*)d_in[10];
    const float* beta = (const float*)d_in[11];
    float* dout = (float*)d_out;

    k_detect_zero<<<(NN + 255) / 256, 256>>>(ei);
    k_convert<<<(EE + 255) / 256, 256>>>(ei);
    k_scan1<<<(NN + 1023) / 1024, 1024>>>();
    k_scan2_wae<<<1, 768>>>((NN + 1023) / 1024, attE, linEW);
    k_scan3<<<(NN + 255) / 256, 256>>>();
    k_scatter<<<(EE + 255) / 256, 256>>>(ea);

    for (int l = 0; l < 2; l++) {
        k_gemm<<<dim3(296, 2), 256>>>(h, l, linW + l * 256 * 64, attS + l * 256, attD + l * 256);
        k_agg<<<(NN * 32 + 255) / 256, 256>>>(bias + l * 64, gamma + l * 64, beta + l * 64, dout, l);
    }
}